// round 15
// baseline (speedup 1.0000x reference)
#include <cuda_runtime.h>
#include <cuda_fp16.h>
#include <cstdint>

// Problem constants
#define Bx    16
#define Sx    1024
#define Dx    768
#define NSx   256
#define Vx    128
#define Cx    6
#define Rx    512
#define RELx  97
#define HIDx  384
#define DISx  20
#define FINx  (Dx + DISx)          // 788
#define KF    (2 * FINx + Dx)      // 2344
#define MROWS (Bx * Rx)            // 8192
#define NVERT (Bx * Vx)            // 2048
#define KD    768
#define BKx   32

// W1 row-block offsets
#define W1_EH   768
#define W1_TAIL 788
#define W1_ET   1556
#define W1_PROD 1576

// Scratch (static device globals — no allocation allowed)
__device__ float g_span[(size_t)Bx * NSx * Dx];
__device__ float g_vert[(size_t)NVERT * Dx];
__device__ __align__(16) __half g_vh[(size_t)NVERT * KD];    // vertex fp16
__device__ __align__(16) __half g_ph[(size_t)MROWS * KD];    // head*tail fp16
__device__ __align__(16) __half g_bv[(size_t)768 * KD];      // [W1a|W1c]^T
__device__ __align__(16) __half g_bp[(size_t)HIDx * KD];     // W1e^T
__device__ __align__(16) __half g_hh[(size_t)MROWS * HIDx];  // hid fp16
__device__ __align__(16) __half g_w2h[(size_t)128 * HIDx];   // W2^T padded
__device__ float g_P[(size_t)NVERT * 768];                   // vertex proj
__device__ float g_acc[(size_t)MROWS * HIDx];                // GEMM_P raw acc
__device__ float g_e1[20 * HIDx];
__device__ float g_e2[20 * HIDx];

// ---------------------------------------------------------------------------
// PTX helpers (sm_80-era only — tcgen05 won't assemble for compute_103)
// ---------------------------------------------------------------------------
__device__ __forceinline__ uint32_t smem_u32(const void* p) {
    uint32_t a;
    asm("{ .reg .u64 t; cvta.to.shared.u64 t, %1; cvt.u32.u64 %0, t; }"
        : "=r"(a) : "l"(p));
    return a;
}

__device__ __forceinline__ void ldsm4(uint32_t* r, uint32_t addr) {
    asm volatile("ldmatrix.sync.aligned.m8n8.x4.shared.b16 {%0,%1,%2,%3}, [%4];"
                 : "=r"(r[0]), "=r"(r[1]), "=r"(r[2]), "=r"(r[3]) : "r"(addr));
}

__device__ __forceinline__ void mma_fp16(float* d, const uint32_t* a,
                                         uint32_t b0, uint32_t b1) {
    asm volatile(
        "mma.sync.aligned.m16n8k16.row.col.f32.f16.f16.f32 "
        "{%0,%1,%2,%3}, {%4,%5,%6,%7}, {%8,%9}, {%0,%1,%2,%3};"
        : "+f"(d[0]), "+f"(d[1]), "+f"(d[2]), "+f"(d[3])
        : "r"(a[0]), "r"(a[1]), "r"(a[2]), "r"(a[3]), "r"(b0), "r"(b1));
}

__device__ __forceinline__ void cp16(uint32_t dst, const void* src) {
    asm volatile("cp.async.cg.shared.global [%0], [%1], 16;"
                 :: "r"(dst), "l"(src));
}
#define CP_COMMIT() asm volatile("cp.async.commit_group;" ::: "memory")
#define CP_WAIT(n)  asm volatile("cp.async.wait_group %0;" :: "n"(n) : "memory")

// ---------------------------------------------------------------------------
// Stage 1: span max-pool.  Width w in [0,7]; starts in [0, S-MAXW) so all 8
// row loads are in-bounds -> issue them unconditionally (MLP=8), then merge
// with a predicated fmax (j <= w).  Row 0 is always valid.
// ---------------------------------------------------------------------------
__global__ void span_kernel(const float* __restrict__ sent,
                            const int* __restrict__ spans) {
    int bs = blockIdx.x;
    int b  = bs / NSx;
    int start = spans[bs * 2 + 0];
    int end   = spans[bs * 2 + 1];
    int w = end - start;
    const float4* base = (const float4*)(sent + ((size_t)b * Sx + start) * Dx);
    int t = threadIdx.x;
    float4 v[8];
    #pragma unroll
    for (int j = 0; j < 8; j++)
        v[j] = base[(size_t)j * (Dx / 4) + t];
    float4 m = v[0];
    #pragma unroll
    for (int j = 1; j < 8; j++) {
        if (j <= w) {
            m.x = fmaxf(m.x, v[j].x); m.y = fmaxf(m.y, v[j].y);
            m.z = fmaxf(m.z, v[j].z); m.w = fmaxf(m.w, v[j].w);
        }
    }
    ((float4*)(g_span + (size_t)bs * Dx))[t] = m;
}

// ---------------------------------------------------------------------------
// Stage 2: vertex masked mean (fp32 + fp16 for GEMM_V)
// ---------------------------------------------------------------------------
__global__ void vertex_kernel(const int* __restrict__ vidx,
                              const int* __restrict__ vmask) {
    int bv = blockIdx.x;
    int b  = bv / Vx;
    int t  = threadIdx.x;             // 0..191
    float4 acc = make_float4(0.f, 0.f, 0.f, 0.f);
    float cnt = 0.f;
    #pragma unroll
    for (int c = 0; c < Cx; c++) {
        int mk = vmask[bv * Cx + c];
        if (mk) {
            int idx = vidx[bv * Cx + c];
            float4 v = ((const float4*)(g_span + ((size_t)b * NSx + idx) * Dx))[t];
            acc.x += v.x; acc.y += v.y; acc.z += v.z; acc.w += v.w;
            cnt += 1.f;
        }
    }
    float inv = 1.f / fmaxf(cnt, 1.f);
    acc.x *= inv; acc.y *= inv; acc.z *= inv; acc.w *= inv;
    ((float4*)(g_vert + (size_t)bv * Dx))[t] = acc;

    size_t o2 = (size_t)bv * (KD / 2) + t * 2;
    ((__half2*)g_vh)[o2]     = __floats2half2_rn(acc.x, acc.y);
    ((__half2*)g_vh)[o2 + 1] = __floats2half2_rn(acc.z, acc.w);
}

// ---------------------------------------------------------------------------
// Stage 3: product features  head∘tail -> fp16  (8192 x 768)
// ---------------------------------------------------------------------------
__global__ void feat_prod(const int* __restrict__ hti) {
    int m = blockIdx.x;
    int b = m / Rx;
    int h  = hti[m * 2 + 0];
    int tl = hti[m * 2 + 1];
    const float4* hp = (const float4*)(g_vert + ((size_t)b * Vx + h)  * Dx);
    const float4* tp = (const float4*)(g_vert + ((size_t)b * Vx + tl) * Dx);
    int t = threadIdx.x;              // 0..191
    float4 a = hp[t], c = tp[t];
    size_t o2 = (size_t)m * (KD / 2) + t * 2;
    ((__half2*)g_ph)[o2]     = __floats2half2_rn(a.x * c.x, a.y * c.y);
    ((__half2*)g_ph)[o2 + 1] = __floats2half2_rn(a.z * c.z, a.w * c.w);
}

// ---------------------------------------------------------------------------
// Stage 3b: merged weight prep (coalesced tile transpose) + distance tables.
// ---------------------------------------------------------------------------
__global__ void prep_all(const float* __restrict__ W1,
                         const float* __restrict__ W2,
                         const float* __restrict__ dis) {
    __shared__ float tile[32][33];
    int idx = blockIdx.x;
    int t  = threadIdx.x;
    int tx = t & 31, ty = t >> 5;       // 32 x 8

    if (idx < 912) {
        int k0, n0;
        const float* src;
        int src_ld, src_guard;
        __half* dst;
        if (idx < 576) {                // Bv: 24 k-tiles x 24 n-tiles
            int kt = idx / 24, nt = idx % 24;
            k0 = kt * 32; n0 = nt * 32;
            if (n0 < 384) { src = W1 + (size_t)k0 * HIDx + n0; }
            else          { src = W1 + (size_t)(W1_TAIL + k0) * HIDx + (n0 - 384); }
            src_ld = HIDx; src_guard = 32;
            dst = g_bv + (size_t)n0 * KD + k0;
        } else if (idx < 864) {         // Bp: 24 k-tiles x 12 n-tiles
            int q = idx - 576;
            int kt = q / 12, nt = q % 12;
            k0 = kt * 32; n0 = nt * 32;
            src = W1 + (size_t)(W1_PROD + k0) * HIDx + n0;
            src_ld = HIDx; src_guard = 32;
            dst = g_bp + (size_t)n0 * KD + k0;
        } else {                        // W2t: 12 k-tiles x 4 n-tiles
            int q = idx - 864;
            int kt = q / 4, nt = q % 4;
            k0 = kt * 32; n0 = nt * 32;
            src = W2 + (size_t)k0 * RELx + n0;
            src_ld = RELx;
            src_guard = (n0 + 32 <= RELx) ? 32 : (RELx > n0 ? RELx - n0 : 0);
            dst = g_w2h + (size_t)n0 * HIDx + k0;
        }
        #pragma unroll
        for (int i = 0; i < 4; i++) {
            int r = i * 8 + ty;
            tile[r][tx] = (tx < src_guard) ? src[(size_t)r * src_ld + tx] : 0.f;
        }
        __syncthreads();
        int KOUT = (idx < 864) ? KD : HIDx;
        #pragma unroll
        for (int i = 0; i < 4; i++) {
            int r = i * 8 + ty;         // n within tile
            dst[(size_t)r * KOUT + tx] = __float2half(tile[tx][r]);
        }
    } else {                            // distance tables
        int q = idx - 912;
        int d = q % 20, which = q / 20;
        int wbase = which ? W1_ET : W1_EH;
        float* outp = which ? g_e2 : g_e1;
        for (int n = t; n < HIDx; n += 256) {
            float s = 0.f;
            #pragma unroll
            for (int j = 0; j < DISx; j++)
                s += dis[d * DISx + j] * W1[(size_t)(wbase + j) * HIDx + n];
            outp[d * HIDx + n] = s;
        }
    }
}

// ---------------------------------------------------------------------------
// hid epilogue: hid = relu(acc + P[h] + P[t] + E1 + E2) -> fp16
// Same add order as the fused version => bit-identical.
// ---------------------------------------------------------------------------
__global__ void hid_epi(const int* __restrict__ hti,
                        const int* __restrict__ dht,
                        const int* __restrict__ dth) {
    int r = blockIdx.x;
    int b = r / Rx;
    int hrow = b * Vx + hti[r * 2 + 0];
    int trow = b * Vx + hti[r * 2 + 1];
    const float2* ac = (const float2*)(g_acc + (size_t)r * HIDx);
    const float2* ph = (const float2*)(g_P + (size_t)hrow * 768);
    const float2* pt = (const float2*)(g_P + (size_t)trow * 768 + HIDx);
    const float2* e1 = (const float2*)(g_e1 + dht[r] * HIDx);
    const float2* e2 = (const float2*)(g_e2 + dth[r] * HIDx);
    int t = threadIdx.x;              // 0..191
    float2 a  = ac[t];
    float2 p0 = ph[t], p1 = pt[t], q0 = e1[t], q1 = e2[t];
    float v0 = fmaxf(a.x + p0.x + p1.x + q0.x + q1.x, 0.f);
    float v1 = fmaxf(a.y + p0.y + p1.y + q0.y + q1.y, 0.f);
    ((__half2*)g_hh)[(size_t)r * (HIDx / 2) + t] = __floats2half2_rn(v0, v1);
}

// ---------------------------------------------------------------------------
// Single-stream fp16 HMMA GEMM: out[M x N] = A[M x K] * B[N x K]^T, fp32 accum
//   BM=128, BN=NF*16; 8 warps (4m x 2n); OCC CTAs/SM (template).
//   4-stage cp.async pipeline; per-chunk ldsm fully hoisted (both ks halves
//   loaded before any MMA -> one load burst, then 16/32 independent HMMAs).
//   MODE 0: plain fp32 store
//   MODE 2: + bias, n<RELx guard, fp32 store (GEMM2 -> out)
// ---------------------------------------------------------------------------
#define PAD 40                          // fp16 elems per smem row (80B stride)
#define NSTG 4                          // pipeline stages

template <int NF, int MODE, int OCC>
__global__ __launch_bounds__(256, OCC) void gemm_fp16(
    const __half* __restrict__ A, const __half* __restrict__ B,
    float* __restrict__ out, int ldc, int K, int nch,
    const float* __restrict__ bias) {
    constexpr int BN    = NF * 16;
    constexpr int ARR_A = 128 * PAD * 2;
    constexpr int ARR_B = BN * PAD * 2;
    constexpr int STG   = ARR_A + ARR_B;

    extern __shared__ char smem[];
    uint32_t sb = smem_u32(smem);
    int t = threadIdx.x, wid = t >> 5, lane = t & 31;
    int n0 = blockIdx.x * BN;
    int m0 = blockIdx.y * 128;
    int wm = (wid & 3) * 32;
    int wn = (wid >> 2) * (NF * 8);

    float acc[2][NF][4];
    #pragma unroll
    for (int i = 0; i < 2; i++)
        #pragma unroll
        for (int j = 0; j < NF; j++)
            #pragma unroll
            for (int q = 0; q < 4; q++) acc[i][j][q] = 0.f;

    auto load_chunk = [&](int k0, int s) {
        uint32_t stg = sb + (uint32_t)s * STG;
        #pragma unroll
        for (int i = 0; i < 2; i++) {               // A: 512 16B chunks
            int e = (i << 8) + t;
            int r = e >> 2;
            int c = e & 3;
            cp16(stg + r * (PAD * 2) + c * 16,
                 A + (size_t)(m0 + r) * K + k0 + c * 8);
        }
        if (t < BN * 4) {                           // B: BN*4 chunks
            int r = t >> 2, c = t & 3;
            cp16(stg + ARR_A + r * (PAD * 2) + c * 16,
                 B + (size_t)(n0 + r) * K + k0 + c * 8);
        }
    };

    #pragma unroll
    for (int i = 0; i < NSTG - 1; i++) {
        if (i < nch) load_chunk(i * BKx, i);
        CP_COMMIT();
    }

    int lr = lane & 15;
    int lc = lane >> 4;

    for (int c = 0; c < nch; c++) {
        CP_WAIT(NSTG - 2);
        __syncthreads();

        int pf = c + NSTG - 1;
        if (pf < nch) load_chunk(pf * BKx, pf & (NSTG - 1));
        CP_COMMIT();

        uint32_t a_base = sb + (uint32_t)(c & (NSTG - 1)) * STG;
        uint32_t b_base = a_base + ARR_A;

        // Hoist ALL fragment loads for both ks halves, then all MMAs.
        uint32_t af[2][2][4];           // [ks][mf]
        uint32_t bf[2][NF * 2];         // [ks]
        #pragma unroll
        for (int ks = 0; ks < 2; ks++) {
            uint32_t koff = (uint32_t)(ks * 16 + lc * 8) * 2;
            #pragma unroll
            for (int mf = 0; mf < 2; mf++) {
                uint32_t ro = (uint32_t)(wm + mf * 16 + lr) * (PAD * 2) + koff;
                ldsm4(af[ks][mf], a_base + ro);
            }
            #pragma unroll
            for (int g = 0; g < NF / 2; g++) {
                uint32_t ro = (uint32_t)(wn + g * 16 + lr) * (PAD * 2) + koff;
                ldsm4(&bf[ks][g * 4], b_base + ro);
            }
        }
        #pragma unroll
        for (int ks = 0; ks < 2; ks++) {
            #pragma unroll
            for (int mf = 0; mf < 2; mf++) {
                #pragma unroll
                for (int nf = 0; nf < NF; nf++) {
                    int bi = (nf >> 1) * 4 + (nf & 1);
                    mma_fp16(acc[mf][nf], af[ks][mf], bf[ks][bi], bf[ks][bi + 2]);
                }
            }
        }
    }

    int row  = lane >> 2;
    int colp = (lane & 3) * 2;
    if (MODE == 0) {
        #pragma unroll
        for (int mf = 0; mf < 2; mf++) {
            #pragma unroll
            for (int nf = 0; nf < NF; nf++) {
                int r0 = m0 + wm + mf * 16 + row;
                int cc = n0 + wn + nf * 8 + colp;
                *(float2*)(out + (size_t)r0 * ldc + cc) =
                    make_float2(acc[mf][nf][0], acc[mf][nf][1]);
                *(float2*)(out + (size_t)(r0 + 8) * ldc + cc) =
                    make_float2(acc[mf][nf][2], acc[mf][nf][3]);
            }
        }
    } else {
        // + bias, guard n < RELx, fp32 -> out
        #pragma unroll
        for (int mf = 0; mf < 2; mf++) {
            #pragma unroll
            for (int rr = 0; rr < 2; rr++) {
                int r = m0 + wm + mf * 16 + row + rr * 8;
                #pragma unroll
                for (int nf = 0; nf < NF; nf++) {
                    int cc = n0 + wn + nf * 8 + colp;
                    if (cc < RELx)
                        out[(size_t)r * RELx + cc] =
                            acc[mf][nf][rr * 2 + 0] + bias[cc];
                    if (cc + 1 < RELx)
                        out[(size_t)r * RELx + cc + 1] =
                            acc[mf][nf][rr * 2 + 1] + bias[cc + 1];
                }
            }
        }
    }
}

#define SMEM_NF4 (NSTG * (128 * PAD * 2 + 64 * PAD * 2))   // 61440
#define SMEM_NF2 (NSTG * (128 * PAD * 2 + 32 * PAD * 2))   // 51200

// ---------------------------------------------------------------------------
// Launch — fork/join stream DAG:
//   s1: prep_all ------------------------- e_prep
//   0 : span -> vertex -(e_vert)-> feat -> [w e_prep] GEMM_P_main
//   s2: [e_vert, e_prep] GEMM_V ---------- e_gv
//   0 : [w e_gv] hid_epi -> GEMM2
// ---------------------------------------------------------------------------
extern "C" void kernel_launch(void* const* d_in, const int* in_sizes, int n_in,
                              void* d_out, int out_size) {
    const float* sent  = (const float*)d_in[0];
    const int*   spans = (const int*)d_in[1];
    const int*   vidx  = (const int*)d_in[3];
    const int*   vmask = (const int*)d_in[4];
    const int*   hti   = (const int*)d_in[5];
    const int*   dht   = (const int*)d_in[7];
    const int*   dth   = (const int*)d_in[8];
    const float* dis   = (const float*)d_in[9];
    const float* W1    = (const float*)d_in[10];
    const float* W2    = (const float*)d_in[11];
    const float* b2    = (const float*)d_in[12];
    float* out = (float*)d_out;

    static cudaStream_t s1 = nullptr, s2 = nullptr;
    static cudaEvent_t e_root = nullptr, e_prep = nullptr, e_vert = nullptr,
                       e_gv = nullptr;
    if (!s1) {
        cudaStreamCreateWithFlags(&s1, cudaStreamNonBlocking);
        cudaStreamCreateWithFlags(&s2, cudaStreamNonBlocking);
        cudaEventCreateWithFlags(&e_root, cudaEventDisableTiming);
        cudaEventCreateWithFlags(&e_prep, cudaEventDisableTiming);
        cudaEventCreateWithFlags(&e_vert, cudaEventDisableTiming);
        cudaEventCreateWithFlags(&e_gv,   cudaEventDisableTiming);
        cudaFuncSetAttribute((const void*)gemm_fp16<2, 0, 4>,
                             cudaFuncAttributeMaxDynamicSharedMemorySize, SMEM_NF2);
        cudaFuncSetAttribute((const void*)gemm_fp16<4, 0, 3>,
                             cudaFuncAttributeMaxDynamicSharedMemorySize, SMEM_NF4);
        cudaFuncSetAttribute((const void*)gemm_fp16<4, 2, 3>,
                             cudaFuncAttributeMaxDynamicSharedMemorySize, SMEM_NF4);
    }

    __half *p_vh, *p_ph, *p_bv, *p_bp, *p_hh, *p_w2h;
    float *p_P, *p_acc;
    cudaGetSymbolAddress((void**)&p_vh,  g_vh);
    cudaGetSymbolAddress((void**)&p_ph,  g_ph);
    cudaGetSymbolAddress((void**)&p_bv,  g_bv);
    cudaGetSymbolAddress((void**)&p_bp,  g_bp);
    cudaGetSymbolAddress((void**)&p_hh,  g_hh);
    cudaGetSymbolAddress((void**)&p_w2h, g_w2h);
    cudaGetSymbolAddress((void**)&p_P,   g_P);
    cudaGetSymbolAddress((void**)&p_acc, g_acc);

    // Fork: prep_all on s1 concurrently with the span->vertex chain.
    cudaEventRecord(e_root, 0);
    cudaStreamWaitEvent(s1, e_root, 0);
    cudaStreamWaitEvent(s2, e_root, 0);

    prep_all<<<952, 256, 0, s1>>>(W1, W2, dis);
    cudaEventRecord(e_prep, s1);

    span_kernel<<<Bx * NSx, 192, 0, 0>>>(sent, spans);
    vertex_kernel<<<NVERT, 192, 0, 0>>>(vidx, vmask);
    cudaEventRecord(e_vert, 0);

    // GEMM_V on s2 (needs vertex + prep), 4 CTAs/SM.
    cudaStreamWaitEvent(s2, e_vert, 0);
    cudaStreamWaitEvent(s2, e_prep, 0);
    gemm_fp16<2, 0, 4><<<dim3(768 / 32, NVERT / 128), 256, SMEM_NF2, s2>>>(
        p_vh, p_bv, p_P, 768, KD, KD / BKx, nullptr);
    cudaEventRecord(e_gv, s2);

    // stream 0: feat, then GEMM_P mainloop (co-runs with GEMM_V on s2).
    feat_prod<<<MROWS, 192, 0, 0>>>(hti);
    cudaStreamWaitEvent(0, e_prep, 0);
    gemm_fp16<4, 0, 3><<<dim3(HIDx / 64, MROWS / 128), 256, SMEM_NF4, 0>>>(
        p_ph, p_bp, p_acc, HIDx, KD, KD / BKx, nullptr);

    // Join: epilogue needs acc + P; then GEMM2.
    cudaStreamWaitEvent(0, e_gv, 0);
    hid_epi<<<MROWS, 192, 0, 0>>>(hti, dht, dth);
    gemm_fp16<4, 2, 3><<<dim3(128 / 64, MROWS / 128), 256, SMEM_NF4, 0>>>(
        p_hh, p_w2h, out, RELx, HIDx, HIDx / BKx, b2);
}